// round 12
// baseline (speedup 1.0000x reference)
#include <cuda_runtime.h>
#include <cuda_bf16.h>
#include <math.h>
#include <stdint.h>

// Problem constants
#define T_DIM 128
#define B_DIM 64
#define H_DIM 512
#define E_DIM 256
#define V_DIM 32000
#define VT_DIM (V_DIM + T_DIM)   // 32128
#define EPSC 1e-10f
#define NCTA_V 250                // V / 128

// ---------------- scratch ----------------
static constexpr size_t OFF_SPART = 0;           // 4*B*T
static constexpr size_t OFF_RAW   = 32768;       // B*T
static constexpr size_t OFF_HW1   = 40960;       // B*H
static constexpr size_t OFF_CTX   = 73728;       // B*H
static constexpr size_t OFF_X     = 106496;      // B*(E+H)
static constexpr size_t OFF_GI    = 155648;      // B*3H
static constexpr size_t OFF_GH    = 253952;      // B*3H
static constexpr size_t OFF_HNEW  = 352256;      // B*H
static constexpr size_t OFF_XP    = 385024;      // B*2H
static constexpr size_t OFF_PMAX  = 450560;      // NCTA_V*B (padded)
static constexpr size_t OFF_PSUM  = 466944;
static constexpr size_t OFF_GEN   = 483328;      // B*V
static constexpr size_t OFF_CIDX  = 2531328;     // B*T ints
static constexpr size_t OFF_CVAL  = 2539520;     // B*T
static constexpr size_t OFF_STATS = 2547712;     // B*8
static constexpr size_t OFF_CS    = 2548224;     // (T*B)*H fp32
static constexpr size_t OFF_ENCH  = 6742528;     // T*B*H bf16 /2
static constexpr size_t OFF_ENCL  = 8839680;
static constexpr size_t OFF_W2H   = 10936832;    // H*H bf16 /2
static constexpr size_t OFF_W2L   = 11067904;
static constexpr size_t OFF_C1H   = 11198976;
static constexpr size_t OFF_C1L   = 11330048;
static constexpr size_t SCRATCH_TOTAL = 11461120;

__device__ __align__(16) float g_scratch[SCRATCH_TOTAL];

// ================= helpers =================
__device__ __forceinline__ uint32_t smem_u32(const void* p) {
    uint32_t a;
    asm("{ .reg .u64 t; cvta.to.shared.u64 t, %1; cvt.u32.u64 %0, t; }" : "=r"(a) : "l"(p));
    return a;
}
__device__ __forceinline__ void ldsm4(uint32_t* r, uint32_t addr) {
    asm volatile("ldmatrix.sync.aligned.m8n8.x4.shared.b16 {%0,%1,%2,%3}, [%4];"
        : "=r"(r[0]), "=r"(r[1]), "=r"(r[2]), "=r"(r[3]) : "r"(addr));
}
__device__ __forceinline__ void mma_bf16(float* c, const uint32_t* a, const uint32_t* b) {
    asm volatile("mma.sync.aligned.m16n8k16.row.col.f32.bf16.bf16.f32 "
        "{%0,%1,%2,%3}, {%4,%5,%6,%7}, {%8,%9}, {%0,%1,%2,%3};"
        : "+f"(c[0]), "+f"(c[1]), "+f"(c[2]), "+f"(c[3])
        : "r"(a[0]), "r"(a[1]), "r"(a[2]), "r"(a[3]), "r"(b[0]), "r"(b[1]));
}
#define CP_ASYNC16(dst, src) \
    asm volatile("cp.async.cg.shared.global [%0], [%1], 16;" :: "r"(dst), "l"(src))
#define CP_COMMIT() asm volatile("cp.async.commit_group;" ::: "memory")
#define CP_WAIT(n)  asm volatile("cp.async.wait_group %0;" :: "n"(n) : "memory")

__device__ __forceinline__ void cvt_split(float4 v, uint2& hi, uint2& lo) {
    uint32_t h01, h23;
    asm("cvt.rn.bf16x2.f32 %0, %1, %2;" : "=r"(h01) : "f"(v.y), "f"(v.x));
    asm("cvt.rn.bf16x2.f32 %0, %1, %2;" : "=r"(h23) : "f"(v.w), "f"(v.z));
    float h0 = __uint_as_float(h01 << 16);
    float h1 = __uint_as_float(h01 & 0xffff0000u);
    float h2 = __uint_as_float(h23 << 16);
    float h3 = __uint_as_float(h23 & 0xffff0000u);
    uint32_t l01, l23;
    asm("cvt.rn.bf16x2.f32 %0, %1, %2;" : "=r"(l01) : "f"(v.y - h1), "f"(v.x - h0));
    asm("cvt.rn.bf16x2.f32 %0, %1, %2;" : "=r"(l23) : "f"(v.w - h3), "f"(v.z - h2));
    hi = make_uint2(h01, h23);
    lo = make_uint2(l01, l23);
}
__device__ __forceinline__ void softmerge(float& m, float& s, float om, float os) {
    float nm = fmaxf(m, om);
    s = s * expf(m - nm) + os * expf(om - nm);
    m = nm;
}

// ================= preconvert (vectorized: float4 in, uint2 x2 out) ======
__global__ void __launch_bounds__(256) k_preconv(
    const float* __restrict__ enc, const float* __restrict__ attn_W,
    const float* __restrict__ c1W,
    uint16_t* __restrict__ ench, uint16_t* __restrict__ encl,
    uint16_t* __restrict__ w2h,  uint16_t* __restrict__ w2l,
    uint16_t* __restrict__ ch,   uint16_t* __restrict__ cl)
{
    const int stride = gridDim.x * blockDim.x;
    const int N1 = (T_DIM * B_DIM * H_DIM) >> 2;   // float4 groups
    uint2 hi, lo;
    for (int i = blockIdx.x * blockDim.x + threadIdx.x; i < N1; i += stride) {
        float4 v = *(const float4*)&enc[(size_t)i * 4];
        cvt_split(v, hi, lo);
        *(uint2*)&ench[(size_t)i * 4] = hi;
        *(uint2*)&encl[(size_t)i * 4] = lo;
    }
    const int N2 = (H_DIM * H_DIM) >> 2;
    for (int i = blockIdx.x * blockDim.x + threadIdx.x; i < N2; i += stride) {
        int e = i * 4;
        int r = e >> 9, c = e & 511;
        float4 v = *(const float4*)&attn_W[(size_t)r * 2 * H_DIM + H_DIM + c];
        cvt_split(v, hi, lo);
        *(uint2*)&w2h[e] = hi;
        *(uint2*)&w2l[e] = lo;
        v = *(const float4*)&c1W[(size_t)r * H_DIM + c];
        cvt_split(v, hi, lo);
        *(uint2*)&ch[e] = hi;
        *(uint2*)&cl[e] = lo;
    }
}

// ================= enc GEMM: preconverted bf16x3, 128x128 tile ===========
// 3-stage cp.async pipeline, 64B swizzled rows, ONE sync per K-chunk, 2 CTA/SM.
static constexpr int TILE64   = 128 * 64;            // 8192 bytes per tile
static constexpr int TGP_STAGE = 4 * TILE64;         // 32768
static constexpr int TGP_SMEM  = 3 * TGP_STAGE;      // 98304

__global__ void __launch_bounds__(256, 2) tgemm_pre(
    const uint16_t* __restrict__ Ah, const uint16_t* __restrict__ Al,
    const uint16_t* __restrict__ Bh, const uint16_t* __restrict__ Bl,
    int K, int lda, int ldb,
    const float* __restrict__ add_bh, const float* __restrict__ bias_n,
    const float* __restrict__ wgt_n,
    float* __restrict__ red_out, float* __restrict__ Cts)
{
    extern __shared__ char smem[];
    const uint32_t sb = smem_u32(smem);
    const int tid = threadIdx.x, lane = tid & 31, warp = tid >> 5;
    const int wy = warp >> 2, wx = warp & 3;
    const int m0 = blockIdx.y * 128, n0 = blockIdx.x * 128;

    float acc[4][4][4];
#pragma unroll
    for (int i = 0; i < 4; i++)
#pragma unroll
        for (int j = 0; j < 4; j++)
#pragma unroll
            for (int q = 0; q < 4; q++) acc[i][j][q] = 0.0f;

    const int nchunk = K >> 5;

    auto load_stage = [&](int st, int c) {
        const int k0 = c << 5;
        const uint32_t base = sb + st * TGP_STAGE;
#pragma unroll
        for (int i = 0; i < 2; i++) {
            int id  = tid + (i << 8);
            int row = id >> 2;
            int ch  = id & 3;
            uint32_t off = row * 64 + ((ch ^ ((row >> 1) & 3)) << 4);
            size_t ao = (size_t)(m0 + row) * lda + k0 + ch * 8;
            size_t bo = (size_t)(n0 + row) * ldb + k0 + ch * 8;
            CP_ASYNC16(base + off,              (const void*)&Ah[ao]);
            CP_ASYNC16(base + TILE64 + off,     (const void*)&Al[ao]);
            CP_ASYNC16(base + 2 * TILE64 + off, (const void*)&Bh[bo]);
            CP_ASYNC16(base + 3 * TILE64 + off, (const void*)&Bl[bo]);
        }
    };
    auto compute = [&](int st) {
        const uint32_t s0 = sb + st * TGP_STAGE;
        const int q = lane >> 3, r = lane & 7;
#pragma unroll
        for (int ks = 0; ks < 32; ks += 16) {
            uint32_t a_hi[4][4], a_lo[4][4], b_hi[4][2], b_lo[4][2];
            {
                int arow = wy * 64 + ((q & 1) ? 8 : 0) + r;
                int acol = ks + ((q & 2) ? 8 : 0);
                uint32_t addr = s0 + arow * 64
                              + ((((acol >> 3) ^ ((arow >> 1) & 3))) << 4);
#pragma unroll
                for (int mt = 0; mt < 4; mt++) {
                    ldsm4(a_hi[mt], addr + mt * (16 * 64));
                    ldsm4(a_lo[mt], addr + TILE64 + mt * (16 * 64));
                }
            }
            {
                int brow = wx * 32 + ((q & 2) ? 8 : 0) + r;
                int bcol = ks + ((q & 1) ? 8 : 0);
                uint32_t addr = s0 + 2 * TILE64 + brow * 64
                              + ((((bcol >> 3) ^ ((brow >> 1) & 3))) << 4);
#pragma unroll
                for (int np = 0; np < 2; np++) {
                    ldsm4(&b_hi[np * 2][0], addr + np * (16 * 64));
                    ldsm4(&b_lo[np * 2][0], addr + TILE64 + np * (16 * 64));
                }
            }
#pragma unroll
            for (int mt = 0; mt < 4; mt++)
#pragma unroll
                for (int nt = 0; nt < 4; nt++)
                    mma_bf16(acc[mt][nt], a_hi[mt], b_hi[nt]);
#pragma unroll
            for (int mt = 0; mt < 4; mt++)
#pragma unroll
                for (int nt = 0; nt < 4; nt++)
                    mma_bf16(acc[mt][nt], a_hi[mt], b_lo[nt]);
#pragma unroll
            for (int mt = 0; mt < 4; mt++)
#pragma unroll
                for (int nt = 0; nt < 4; nt++)
                    mma_bf16(acc[mt][nt], a_lo[mt], b_hi[nt]);
        }
    };

    load_stage(0, 0); CP_COMMIT();
    if (nchunk > 1) { load_stage(1, 1); CP_COMMIT(); }
    for (int c = 0; c < nchunk; c++) {
        if (c + 1 < nchunk) { CP_WAIT(1); } else { CP_WAIT(0); }
        __syncthreads();
        compute(c % 3);
        if (c + 2 < nchunk) { load_stage((c + 2) % 3, c + 2); CP_COMMIT(); }
    }
    __syncthreads();

    const int g = lane >> 2, tig = lane & 3;

    if (red_out) {
        float* red = (float*)smem;
#pragma unroll
        for (int mt = 0; mt < 4; mt++) {
            int rl0 = wy * 64 + mt * 16 + g;
            int rl1 = rl0 + 8;
            int b0 = (m0 + rl0) & 63, b1 = (m0 + rl1) & 63;
            float p0 = 0.f, p1 = 0.f;
#pragma unroll
            for (int nt = 0; nt < 4; nt++) {
                int col = n0 + wx * 32 + nt * 8 + tig * 2;
#pragma unroll
                for (int cc = 0; cc < 2; cc++) {
                    int cg = col + cc;
                    float bias = bias_n[cg];
                    float a0 = add_bh[(size_t)b0 * H_DIM + cg];
                    float a1 = add_bh[(size_t)b1 * H_DIM + cg];
                    float w  = wgt_n[cg];
                    p0 += w * tanhf(acc[mt][nt][cc]     + a0 + bias);
                    p1 += w * tanhf(acc[mt][nt][2 + cc] + a1 + bias);
                }
            }
            p0 += __shfl_xor_sync(0xffffffffu, p0, 1);
            p0 += __shfl_xor_sync(0xffffffffu, p0, 2);
            p1 += __shfl_xor_sync(0xffffffffu, p1, 1);
            p1 += __shfl_xor_sync(0xffffffffu, p1, 2);
            if (tig == 0) { red[wx * 128 + rl0] = p0; red[wx * 128 + rl1] = p1; }
        }
        __syncthreads();
        if (tid < 128) {
            float s = red[tid] + red[128 + tid] + red[256 + tid] + red[384 + tid];
            int m = m0 + tid;
            red_out[(size_t)blockIdx.x * (B_DIM * T_DIM) + (m & 63) * T_DIM + (m >> 6)] = s;
        }
        return;
    }

#pragma unroll
    for (int mt = 0; mt < 4; mt++) {
        int row0 = m0 + wy * 64 + mt * 16 + g;
#pragma unroll
        for (int nt = 0; nt < 4; nt++) {
            int col = n0 + wx * 32 + nt * 8 + tig * 2;
            float bv0 = bias_n[col], bv1 = bias_n[col + 1];
            *(float2*)&Cts[(size_t)row0 * H_DIM + col] =
                make_float2(tanhf(acc[mt][nt][0] + bv0), tanhf(acc[mt][nt][1] + bv1));
            *(float2*)&Cts[(size_t)(row0 + 8) * H_DIM + col] =
                make_float2(tanhf(acc[mt][nt][2] + bv0), tanhf(acc[mt][nt][3] + bv1));
        }
    }
}

// ================= small GEMM: cvt-in-kernel bf16x3, 64x128 tile =========
static constexpr int ROWB = 80;
static constexpr int TILEA  = 64 * ROWB;
static constexpr int TILEB  = 128 * ROWB;
static constexpr int STAGEB = 2 * TILEA + 2 * TILEB;  // 30720
static constexpr int TGC_SMEM = 2 * STAGEB;           // 61440

__global__ void __launch_bounds__(256, 2) tgemm_cvt(
    const float* __restrict__ A, const float* __restrict__ B, float* __restrict__ C,
    int M_A, int K, int lda, int ldb, int ldc,
    const float* __restrict__ pb, float* __restrict__ pmax, float* __restrict__ psum)
{
    extern __shared__ char smem[];
    const uint32_t sb = smem_u32(smem);
    const int tid = threadIdx.x, lane = tid & 31, warp = tid >> 5;
    const int wy = warp >> 2, wx = warp & 3;
    const int m0 = blockIdx.y * 64, n0 = blockIdx.x * 128;

    float acc[2][4][4];
#pragma unroll
    for (int i = 0; i < 2; i++)
#pragma unroll
        for (int j = 0; j < 4; j++)
#pragma unroll
            for (int q = 0; q < 4; q++) acc[i][j][q] = 0.0f;

    const int nchunk = K >> 5;
    float4 ra[2], rb[4];

    auto load_regs = [&](int c) {
        const int k0 = c << 5;
#pragma unroll
        for (int i = 0; i < 2; i++) {
            int id = tid + (i << 8);
            int row = id >> 3, kq = id & 7;
            ra[i] = (m0 + row < M_A)
                  ? *(const float4*)&A[(size_t)(m0 + row) * lda + k0 + (kq << 2)]
                  : make_float4(0.f, 0.f, 0.f, 0.f);
        }
#pragma unroll
        for (int i = 0; i < 4; i++) {
            int id = tid + (i << 8);
            int row = id >> 3, kq = id & 7;
            rb[i] = *(const float4*)&B[(size_t)(n0 + row) * ldb + k0 + (kq << 2)];
        }
    };
    auto store_smem = [&](int st) {
        char* base = smem + st * STAGEB;
        uint2 hi, lo;
#pragma unroll
        for (int i = 0; i < 2; i++) {
            int id = tid + (i << 8);
            int row = id >> 3, kq = id & 7;
            int off = row * ROWB + (kq << 3);
            cvt_split(ra[i], hi, lo);
            *(uint2*)(base + off)         = hi;
            *(uint2*)(base + TILEA + off) = lo;
        }
#pragma unroll
        for (int i = 0; i < 4; i++) {
            int id = tid + (i << 8);
            int row = id >> 3, kq = id & 7;
            int off = row * ROWB + (kq << 3);
            cvt_split(rb[i], hi, lo);
            *(uint2*)(base + 2 * TILEA + off)         = hi;
            *(uint2*)(base + 2 * TILEA + TILEB + off) = lo;
        }
    };
    auto compute = [&](int st) {
        const uint32_t s0 = sb + st * STAGEB;
        const int q = lane >> 3, r = lane & 7;
#pragma unroll
        for (int ks = 0; ks < 32; ks += 16) {
            uint32_t a_hi[2][4], a_lo[2][4], b_hi[4][2], b_lo[4][2];
            {
                int arow = wy * 32 + ((q & 1) ? 8 : 0) + r;
                int acol = ks + ((q & 2) ? 8 : 0);
                uint32_t addr = s0 + arow * ROWB + acol * 2;
#pragma unroll
                for (int mt = 0; mt < 2; mt++) {
                    ldsm4(a_hi[mt], addr + mt * (16 * ROWB));
                    ldsm4(a_lo[mt], addr + TILEA + mt * (16 * ROWB));
                }
            }
            {
                int brow = wx * 32 + ((q & 2) ? 8 : 0) + r;
                int bcol = ks + ((q & 1) ? 8 : 0);
                uint32_t addr = s0 + 2 * TILEA + brow * ROWB + bcol * 2;
#pragma unroll
                for (int np = 0; np < 2; np++) {
                    ldsm4(&b_hi[np * 2][0], addr + np * (16 * ROWB));
                    ldsm4(&b_lo[np * 2][0], addr + TILEB + np * (16 * ROWB));
                }
            }
#pragma unroll
            for (int mt = 0; mt < 2; mt++)
#pragma unroll
                for (int nt = 0; nt < 4; nt++)
                    mma_bf16(acc[mt][nt], a_hi[mt], b_hi[nt]);
#pragma unroll
            for (int mt = 0; mt < 2; mt++)
#pragma unroll
                for (int nt = 0; nt < 4; nt++)
                    mma_bf16(acc[mt][nt], a_hi[mt], b_lo[nt]);
#pragma unroll
            for (int mt = 0; mt < 2; mt++)
#pragma unroll
                for (int nt = 0; nt < 4; nt++)
                    mma_bf16(acc[mt][nt], a_lo[mt], b_hi[nt]);
        }
    };

    load_regs(0);
    store_smem(0);
    if (nchunk > 1) load_regs(1);
    __syncthreads();
    for (int c = 0; c < nchunk; c++) {
        if (c + 1 < nchunk) store_smem((c + 1) & 1);
        if (c + 2 < nchunk) load_regs(c + 2);
        compute(c & 1);
        __syncthreads();
    }

    const int g = lane >> 2, tig = lane & 3;

    if (pmax) {
        float lm[4], ls[4];
#pragma unroll
        for (int sl = 0; sl < 4; sl++) { lm[sl] = -1e30f; ls[sl] = 0.0f; }
#pragma unroll
        for (int mt = 0; mt < 2; mt++) {
            int r0 = m0 + wy * 32 + mt * 16 + g;
            int r1 = r0 + 8;
#pragma unroll
            for (int nt = 0; nt < 4; nt++) {
                int col = n0 + wx * 32 + nt * 8 + tig * 2;
                float pb0 = pb[col], pb1 = pb[col + 1];
                float v00 = acc[mt][nt][0], v01 = acc[mt][nt][1];
                float v10 = acc[mt][nt][2], v11 = acc[mt][nt][3];
                *(float2*)&C[(size_t)r0 * ldc + col] = make_float2(v00, v01);
                *(float2*)&C[(size_t)r1 * ldc + col] = make_float2(v10, v11);
                softmerge(lm[mt * 2], ls[mt * 2], v00 + pb0, 1.0f);
                softmerge(lm[mt * 2], ls[mt * 2], v01 + pb1, 1.0f);
                softmerge(lm[mt * 2 + 1], ls[mt * 2 + 1], v10 + pb0, 1.0f);
                softmerge(lm[mt * 2 + 1], ls[mt * 2 + 1], v11 + pb1, 1.0f);
            }
        }
#pragma unroll
        for (int d = 1; d <= 2; d <<= 1)
#pragma unroll
            for (int sl = 0; sl < 4; sl++) {
                float om = __shfl_xor_sync(0xffffffffu, lm[sl], d);
                float os = __shfl_xor_sync(0xffffffffu, ls[sl], d);
                softmerge(lm[sl], ls[sl], om, os);
            }
        float* pm = (float*)smem;
        float* ps = pm + 256;
        if (tig == 0) {
#pragma unroll
            for (int sl = 0; sl < 4; sl++) {
                int row = wy * 32 + sl * 8 + g;
                pm[wx * 64 + row] = lm[sl];
                ps[wx * 64 + row] = ls[sl];
            }
        }
        __syncthreads();
        if (tid < 64) {
            float m = pm[tid], s = ps[tid];
            softmerge(m, s, pm[64 + tid],  ps[64 + tid]);
            softmerge(m, s, pm[128 + tid], ps[128 + tid]);
            softmerge(m, s, pm[192 + tid], ps[192 + tid]);
            pmax[(size_t)blockIdx.x * B_DIM + tid] = m;
            psum[(size_t)blockIdx.x * B_DIM + tid] = s;
        }
        return;
    }

#pragma unroll
    for (int mt = 0; mt < 2; mt++) {
        int row0 = m0 + wy * 32 + mt * 16 + g;
#pragma unroll
        for (int nt = 0; nt < 4; nt++) {
            int col = n0 + wx * 32 + nt * 8 + tig * 2;
            if (row0 < M_A) {
                *(float2*)&C[(size_t)row0 * ldc + col] = make_float2(acc[mt][nt][0], acc[mt][nt][1]);
                *(float2*)&C[(size_t)(row0 + 8) * ldc + col] = make_float2(acc[mt][nt][2], acc[mt][nt][3]);
            }
        }
    }
}

// ================= elementwise / reduction kernels =================

__global__ void __launch_bounds__(128) k_attn(
    const float* __restrict__ part, const int* __restrict__ z,
    const float* __restrict__ emb,  const float* __restrict__ enc,
    float* __restrict__ ctx, float* __restrict__ x)
{
    int b = blockIdx.x, q = blockIdx.y, tid = threadIdx.x;
    __shared__ float al[T_DIM];
    __shared__ float sm[T_DIM];
    {
        int idx = b * T_DIM + tid;
        float v = part[idx] + part[B_DIM * T_DIM + idx]
                + part[2 * B_DIM * T_DIM + idx] + part[3 * B_DIM * T_DIM + idx];
        al[tid] = v; sm[tid] = v;
    }
    __syncthreads();
    for (int o = 64; o > 0; o >>= 1) { if (tid < o) sm[tid] = fmaxf(sm[tid], sm[tid + o]); __syncthreads(); }
    float mx = sm[0]; __syncthreads();
    { float e = expf(al[tid] - mx); al[tid] = e; sm[tid] = e; }
    __syncthreads();
    for (int o = 64; o > 0; o >>= 1) { if (tid < o) sm[tid] += sm[tid + o]; __syncthreads(); }
    float inv = 1.0f / sm[0];

    int h = q * 128 + tid;
    const float* eb = enc + (size_t)b * H_DIM + h;
    float acc = 0.0f;
#pragma unroll 8
    for (int t = 0; t < T_DIM; t++)
        acc += al[t] * eb[(size_t)t * B_DIM * H_DIM];
    acc *= inv;
    ctx[b * H_DIM + h] = acc;
    x[(size_t)b * (E_DIM + H_DIM) + E_DIM + h] = acc;
    if (q == 0) {
        x[(size_t)b * (E_DIM + H_DIM) + tid]       = emb[(size_t)z[b] * E_DIM + tid];
        x[(size_t)b * (E_DIM + H_DIM) + 128 + tid] = emb[(size_t)z[b] * E_DIM + 128 + tid];
    }
}

__global__ void k_gru(const float* __restrict__ gi, const float* __restrict__ gh,
                      const float* __restrict__ bih, const float* __restrict__ bhh,
                      const float* __restrict__ h_prev, const float* __restrict__ ctx,
                      float* __restrict__ hnew, float* __restrict__ xp,
                      float* __restrict__ out)
{
    int b = blockIdx.x, h = threadIdx.x;
    const float* gib = gi + (size_t)b * 3 * H_DIM;
    const float* ghb = gh + (size_t)b * 3 * H_DIM;
    float ir  = gib[h]              + bih[h];
    float iz  = gib[H_DIM + h]      + bih[H_DIM + h];
    float in_ = gib[2 * H_DIM + h]  + bih[2 * H_DIM + h];
    float hr  = ghb[h]              + bhh[h];
    float hz  = ghb[H_DIM + h]      + bhh[H_DIM + h];
    float hn  = ghb[2 * H_DIM + h]  + bhh[2 * H_DIM + h];
    float r  = 1.0f / (1.0f + expf(-(ir + hr)));
    float zz = 1.0f / (1.0f + expf(-(iz + hz)));
    float n  = tanhf(in_ + r * hn);
    float hp = h_prev[b * H_DIM + h];
    float v  = (1.0f - zz) * n + zz * hp;
    hnew[b * H_DIM + h] = v;
    out[b * H_DIM + h] = v;
    out[B_DIM * H_DIM + b * H_DIM + h] = v;
    xp[b * 2 * H_DIM + h] = v;
    xp[b * 2 * H_DIM + H_DIM + h] = ctx[b * H_DIM + h];
}

__global__ void k_raw(const float* __restrict__ cs, const float* __restrict__ hnew,
                      float* __restrict__ raw)
{
    int warp = (blockIdx.x * blockDim.x + threadIdx.x) >> 5;
    int lane = threadIdx.x & 31;
    if (warp >= T_DIM * B_DIM) return;
    int b = warp % B_DIM;
    const float4* e4 = (const float4*)(cs + (size_t)warp * H_DIM);
    const float4* h4 = (const float4*)(hnew + (size_t)b * H_DIM);
    float s = 0.0f;
#pragma unroll
    for (int i = lane; i < H_DIM / 4; i += 32) {
        float4 e = e4[i], h = h4[i];
        s += e.x * h.x + e.y * h.y + e.z * h.z + e.w * h.w;
    }
#pragma unroll
    for (int o = 16; o > 0; o >>= 1) s += __shfl_down_sync(0xffffffffu, s, o);
    if (lane == 0) raw[b * T_DIM + (warp / B_DIM)] = s;
}

__global__ void k_copystats(const float* __restrict__ raw, const int* __restrict__ u_input,
                            int* __restrict__ cidx, float* __restrict__ cval,
                            float* __restrict__ stats)
{
    int b = blockIdx.x, t = threadIdx.x;
    __shared__ float sm[T_DIM];
    __shared__ float exm[T_DIM];
    __shared__ int   sidx[T_DIM];
    float v = raw[b * T_DIM + t];
    sm[t] = v; __syncthreads();
    for (int o = 64; o > 0; o >>= 1) { if (t < o) sm[t] = fmaxf(sm[t], sm[t + o]); __syncthreads(); }
    float cmax = sm[0]; __syncthreads();

    float e = expf(v - cmax);
    int tok = u_input[t * B_DIM + b];
    sidx[t] = (tok == 2) ? (V_DIM + t) : tok;
    float em = (tok != 0) ? e : 0.0f;
    exm[t] = em;

    sm[t] = e; __syncthreads();
    for (int o = 64; o > 0; o >>= 1) { if (t < o) sm[t] += sm[t + o]; __syncthreads(); }
    float total = sm[0]; __syncthreads();

    sm[t] = em; __syncthreads();
    for (int o = 64; o > 0; o >>= 1) { if (t < o) sm[t] += sm[t + o]; __syncthreads(); }
    float sum_exm = sm[0]; __syncthreads();

    int idx = sidx[t];
    bool first = true;
    for (int i = 0; i < t; i++) if (sidx[i] == idx) { first = false; break; }
    float a = 0.0f;
    if (first) {
        for (int i = t; i < T_DIM; i++) if (sidx[i] == idx) a += exm[i];
        cidx[b * T_DIM + t] = idx;
    } else {
        cidx[b * T_DIM + t] = -1;
    }
    cval[b * T_DIM + t] = a;

    sm[t] = a; __syncthreads();
    for (int o = 64; o > 0; o >>= 1) { if (t < o) sm[t] = fmaxf(sm[t], sm[t + o]); __syncthreads(); }
    if (t == 0) {
        stats[b * 8 + 0] = cmax;
        stats[b * 8 + 1] = total;
        stats[b * 8 + 2] = sum_exm;
        stats[b * 8 + 3] = sm[0];
    }
}

__global__ void __launch_bounds__(256) k_reduce(
    const float* __restrict__ pmax, const float* __restrict__ psum,
    float* __restrict__ stats)
{
    int b = blockIdx.x, tid = threadIdx.x;
    float m = -1e30f, s = 0.0f;
    for (int i = tid; i < NCTA_V; i += 256)
        softmerge(m, s, pmax[(size_t)i * B_DIM + b], psum[(size_t)i * B_DIM + b]);
    __shared__ float ms[256], ss[256];
    ms[tid] = m; ss[tid] = s; __syncthreads();
    for (int o = 128; o > 0; o >>= 1) {
        if (tid < o) {
            float mm = ms[tid], sv = ss[tid];
            softmerge(mm, sv, ms[tid + o], ss[tid + o]);
            ms[tid] = mm; ss[tid] = sv;
        }
        __syncthreads();
    }
    if (tid == 0) {
        float cmax = stats[b * 8 + 0];
        float total = stats[b * 8 + 1];
        float sum_exm = stats[b * 8 + 2];
        float smax = stats[b * 8 + 3];
        float mg = ms[0], sg = ss[0];
        float mc = logf(EPSC * total + (1.0f - EPSC) * smax) + cmax;
        float M = fmaxf(mg, mc);
        float A = expf(cmax - M);
        float S = sg * expf(mg - M)
                + A * (EPSC * total * (float)VT_DIM + (1.0f - EPSC) * sum_exm);
        stats[b * 8 + 4] = M;
        stats[b * 8 + 5] = S;
        stats[b * 8 + 6] = A;
    }
}

// vectorized final: 4 elements per thread (V and VT both divisible by 4)
__global__ void __launch_bounds__(256) k_final(
    const float* __restrict__ gen, const float* __restrict__ projb,
    const float* __restrict__ stats, float* __restrict__ out)
{
    int i4 = blockIdx.x * blockDim.x + threadIdx.x;
    if (i4 >= (B_DIM * VT_DIM) / 4) return;
    int b = i4 / (VT_DIM / 4);
    int j = (i4 % (VT_DIM / 4)) * 4;
    float M = stats[b * 8 + 4];
    float S = stats[b * 8 + 5];
    float A = stats[b * 8 + 6];
    float total = stats[b * 8 + 1];
    float invS = 1.0f / S;
    float base = A * EPSC * total * invS;
    float4 r = make_float4(base, base, base, base);
    if (j < V_DIM) {
        float4 g = *(const float4*)&gen[(size_t)b * V_DIM + j];
        float4 p = *(const float4*)&projb[j];
        r.x += __expf(g.x + p.x - M) * invS;
        r.y += __expf(g.y + p.y - M) * invS;
        r.z += __expf(g.z + p.z - M) * invS;
        r.w += __expf(g.w + p.w - M) * invS;
    }
    *(float4*)&out[2 * B_DIM * H_DIM + (size_t)b * VT_DIM + j] = r;
}

__global__ void k_scatter(const int* __restrict__ cidx, const float* __restrict__ cval,
                          const float* __restrict__ stats, float* __restrict__ out)
{
    int b = blockIdx.x, t = threadIdx.x;
    int id = cidx[b * T_DIM + t];
    if (id >= 0) {
        float S = stats[b * 8 + 5];
        float A = stats[b * 8 + 6];
        out[2 * B_DIM * H_DIM + (size_t)b * VT_DIM + id] +=
            A * (1.0f - EPSC) * cval[b * T_DIM + t] / S;
    }
}

// ================= host launcher =================
extern "C" void kernel_launch(void* const* d_in, const int* in_sizes, int n_in,
                              void* d_out, int out_size)
{
    const float* u_enc  = (const float*)d_in[0];
    const int*   z_tm1  = (const int*)  d_in[1];
    const float* h0     = (const float*)d_in[2];
    const int*   u_inp  = (const int*)  d_in[3];
    const float* emb    = (const float*)d_in[4];
    const float* attn_W = (const float*)d_in[5];
    const float* attn_b = (const float*)d_in[6];
    const float* attn_v = (const float*)d_in[7];
    const float* gWih   = (const float*)d_in[8];
    const float* gWhh   = (const float*)d_in[9];
    const float* gbih   = (const float*)d_in[10];
    const float* gbhh   = (const float*)d_in[11];
    const float* projW  = (const float*)d_in[12];
    const float* projb  = (const float*)d_in[13];
    const float* c1W    = (const float*)d_in[14];
    const float* c1b    = (const float*)d_in[15];
    float* out = (float*)d_out;

    float* base = nullptr;
    cudaGetSymbolAddress((void**)&base, g_scratch);
    float* spart = base + OFF_SPART;
    float* raw   = base + OFF_RAW;
    float* hW1   = base + OFF_HW1;
    float* ctx   = base + OFF_CTX;
    float* x     = base + OFF_X;
    float* gi    = base + OFF_GI;
    float* gh    = base + OFF_GH;
    float* hnew  = base + OFF_HNEW;
    float* xp    = base + OFF_XP;
    float* pmax  = base + OFF_PMAX;
    float* psum  = base + OFF_PSUM;
    float* gen   = base + OFF_GEN;
    int*   cidx  = (int*)(base + OFF_CIDX);
    float* cval  = base + OFF_CVAL;
    float* stats = base + OFF_STATS;
    float* cs    = base + OFF_CS;
    uint16_t* ench = (uint16_t*)(base + OFF_ENCH);
    uint16_t* encl = (uint16_t*)(base + OFF_ENCL);
    uint16_t* w2h  = (uint16_t*)(base + OFF_W2H);
    uint16_t* w2l  = (uint16_t*)(base + OFF_W2L);
    uint16_t* c1h  = (uint16_t*)(base + OFF_C1H);
    uint16_t* c1l  = (uint16_t*)(base + OFF_C1L);

    static cudaStream_t s1 = nullptr;
    static cudaEvent_t evFork, evHW1, evGh, evEng, evGru, evCst;
    if (!s1) {
        cudaStreamCreateWithFlags(&s1, cudaStreamNonBlocking);
        cudaEventCreateWithFlags(&evFork, cudaEventDisableTiming);
        cudaEventCreateWithFlags(&evHW1,  cudaEventDisableTiming);
        cudaEventCreateWithFlags(&evGh,   cudaEventDisableTiming);
        cudaEventCreateWithFlags(&evEng,  cudaEventDisableTiming);
        cudaEventCreateWithFlags(&evGru,  cudaEventDisableTiming);
        cudaEventCreateWithFlags(&evCst,  cudaEventDisableTiming);
        cudaFuncSetAttribute(tgemm_pre, cudaFuncAttributeMaxDynamicSharedMemorySize, TGP_SMEM);
        cudaFuncSetAttribute(tgemm_cvt, cudaFuncAttributeMaxDynamicSharedMemorySize, TGC_SMEM);
    }

    const int MROWS = T_DIM * B_DIM;  // 8192

    cudaEventRecord(evFork, 0);
    cudaStreamWaitEvent(s1, evFork, 0);

    // s1: hW1 ; gh (depend only on h0) — overlap preconv on s0
    tgemm_cvt<<<dim3(H_DIM / 128, 1), 256, TGC_SMEM, s1>>>(
        h0, attn_W, hW1, B_DIM, H_DIM, H_DIM, 2 * H_DIM, H_DIM, nullptr, nullptr, nullptr);
    cudaEventRecord(evHW1, s1);
    tgemm_cvt<<<dim3(3 * H_DIM / 128, 1), 256, TGC_SMEM, s1>>>(
        h0, gWhh, gh, B_DIM, H_DIM, H_DIM, H_DIM, 3 * H_DIM, nullptr, nullptr, nullptr);
    cudaEventRecord(evGh, s1);

    // s0: preconvert (vectorized)
    k_preconv<<<1024, 256>>>(u_enc, attn_W, c1W, ench, encl, w2h, w2l, c1h, c1l);

    // s0: energy GEMM (solo — no contention) + attn
    cudaStreamWaitEvent(0, evHW1, 0);
    tgemm_pre<<<dim3(H_DIM / 128, MROWS / 128), 256, TGP_SMEM>>>(
        ench, encl, w2h, w2l, H_DIM, H_DIM, H_DIM,
        hW1, attn_b, attn_v, spart, nullptr);
    cudaEventRecord(evEng, 0);
    k_attn<<<dim3(B_DIM, 4), 128>>>(spart, z_tm1, emb, u_enc, ctx, x);

    // s1: copy GEMM AFTER energy -> overlaps attn/gi/gru/proj on s0
    cudaStreamWaitEvent(s1, evEng, 0);
    tgemm_pre<<<dim3(H_DIM / 128, MROWS / 128), 256, TGP_SMEM, s1>>>(
        ench, encl, c1h, c1l, H_DIM, H_DIM, H_DIM,
        nullptr, c1b, nullptr, nullptr, cs);

    // s0: gi GEMM ; gru
    tgemm_cvt<<<dim3(3 * H_DIM / 128, 1), 256, TGC_SMEM>>>(
        x, gWih, gi, B_DIM, E_DIM + H_DIM, E_DIM + H_DIM, E_DIM + H_DIM, 3 * H_DIM,
        nullptr, nullptr, nullptr);
    cudaStreamWaitEvent(0, evGh, 0);
    k_gru<<<B_DIM, H_DIM>>>(gi, gh, gbih, gbhh, h0, ctx, hnew, xp, out);
    cudaEventRecord(evGru, 0);

    // s1: raw + copystats (after copy GEMM and gru; hidden under proj)
    cudaStreamWaitEvent(s1, evGru, 0);
    k_raw<<<MROWS / 8, 256, 0, s1>>>(cs, hnew, raw);
    k_copystats<<<B_DIM, T_DIM, 0, s1>>>(raw, u_inp, cidx, cval, stats);
    cudaEventRecord(evCst, s1);

    // s0: proj GEMM with fused store + softmax partials
    tgemm_cvt<<<dim3(NCTA_V, 1), 256, TGC_SMEM>>>(
        xp, projW, gen, B_DIM, 2 * H_DIM, 2 * H_DIM, 2 * H_DIM, V_DIM,
        projb, pmax, psum);

    // join + tail
    cudaStreamWaitEvent(0, evCst, 0);
    k_reduce<<<B_DIM, 256>>>(pmax, psum, stats);
    k_final<<<(B_DIM * VT_DIM / 4 + 255) / 256, 256>>>(gen, projb, stats, out);
    k_scatter<<<B_DIM, T_DIM>>>(cidx, cval, stats, out);
}

// round 13
// speedup vs baseline: 1.0952x; 1.0952x over previous
#include <cuda_runtime.h>
#include <cuda_bf16.h>
#include <math.h>
#include <stdint.h>

// Problem constants
#define T_DIM 128
#define B_DIM 64
#define H_DIM 512
#define E_DIM 256
#define V_DIM 32000
#define VT_DIM (V_DIM + T_DIM)   // 32128
#define EPSC 1e-10f
#define NCTA_V 250                // V / 128

// ---------------- scratch ----------------
static constexpr size_t OFF_SPART = 0;           // 4*B*T
static constexpr size_t OFF_RAW   = 32768;       // B*T
static constexpr size_t OFF_HW1   = 40960;       // B*H
static constexpr size_t OFF_CTX   = 73728;       // B*H
static constexpr size_t OFF_X     = 106496;      // B*(E+H)
static constexpr size_t OFF_GI    = 155648;      // B*3H
static constexpr size_t OFF_GH    = 253952;      // B*3H
static constexpr size_t OFF_HNEW  = 352256;      // B*H
static constexpr size_t OFF_XP    = 385024;      // B*2H
static constexpr size_t OFF_PMAX  = 450560;      // NCTA_V*B (padded)
static constexpr size_t OFF_PSUM  = 466944;
static constexpr size_t OFF_GEN   = 483328;      // B*V
static constexpr size_t OFF_CIDX  = 2531328;     // B*T ints
static constexpr size_t OFF_CVAL  = 2539520;     // B*T
static constexpr size_t OFF_STATS = 2547712;     // B*8
static constexpr size_t OFF_CS    = 2548224;     // (T*B)*H fp32
static constexpr size_t OFF_ENCH  = 6742528;     // T*B*H bf16 /2
static constexpr size_t OFF_ENCL  = 8839680;
static constexpr size_t OFF_W2H   = 10936832;    // H*H bf16 /2
static constexpr size_t OFF_W2L   = 11067904;
static constexpr size_t OFF_C1H   = 11198976;
static constexpr size_t OFF_C1L   = 11330048;
static constexpr size_t SCRATCH_TOTAL = 11461120;

__device__ __align__(16) float g_scratch[SCRATCH_TOTAL];

// ================= helpers =================
__device__ __forceinline__ uint32_t smem_u32(const void* p) {
    uint32_t a;
    asm("{ .reg .u64 t; cvta.to.shared.u64 t, %1; cvt.u32.u64 %0, t; }" : "=r"(a) : "l"(p));
    return a;
}
__device__ __forceinline__ void ldsm4(uint32_t* r, uint32_t addr) {
    asm volatile("ldmatrix.sync.aligned.m8n8.x4.shared.b16 {%0,%1,%2,%3}, [%4];"
        : "=r"(r[0]), "=r"(r[1]), "=r"(r[2]), "=r"(r[3]) : "r"(addr));
}
__device__ __forceinline__ void mma_bf16(float* c, const uint32_t* a, const uint32_t* b) {
    asm volatile("mma.sync.aligned.m16n8k16.row.col.f32.bf16.bf16.f32 "
        "{%0,%1,%2,%3}, {%4,%5,%6,%7}, {%8,%9}, {%0,%1,%2,%3};"
        : "+f"(c[0]), "+f"(c[1]), "+f"(c[2]), "+f"(c[3])
        : "r"(a[0]), "r"(a[1]), "r"(a[2]), "r"(a[3]), "r"(b[0]), "r"(b[1]));
}
#define CP_ASYNC16(dst, src) \
    asm volatile("cp.async.cg.shared.global [%0], [%1], 16;" :: "r"(dst), "l"(src))
#define CP_COMMIT() asm volatile("cp.async.commit_group;" ::: "memory")
#define CP_WAIT(n)  asm volatile("cp.async.wait_group %0;" :: "n"(n) : "memory")

__device__ __forceinline__ void cvt_split(float4 v, uint2& hi, uint2& lo) {
    uint32_t h01, h23;
    asm("cvt.rn.bf16x2.f32 %0, %1, %2;" : "=r"(h01) : "f"(v.y), "f"(v.x));
    asm("cvt.rn.bf16x2.f32 %0, %1, %2;" : "=r"(h23) : "f"(v.w), "f"(v.z));
    float h0 = __uint_as_float(h01 << 16);
    float h1 = __uint_as_float(h01 & 0xffff0000u);
    float h2 = __uint_as_float(h23 << 16);
    float h3 = __uint_as_float(h23 & 0xffff0000u);
    uint32_t l01, l23;
    asm("cvt.rn.bf16x2.f32 %0, %1, %2;" : "=r"(l01) : "f"(v.y - h1), "f"(v.x - h0));
    asm("cvt.rn.bf16x2.f32 %0, %1, %2;" : "=r"(l23) : "f"(v.w - h3), "f"(v.z - h2));
    hi = make_uint2(h01, h23);
    lo = make_uint2(l01, l23);
}
__device__ __forceinline__ void softmerge(float& m, float& s, float om, float os) {
    float nm = fmaxf(m, om);
    s = s * expf(m - nm) + os * expf(om - nm);
    m = nm;
}

// ================= preconvert (vectorized) =================
__global__ void __launch_bounds__(256) k_preconv(
    const float* __restrict__ enc, const float* __restrict__ attn_W,
    const float* __restrict__ c1W,
    uint16_t* __restrict__ ench, uint16_t* __restrict__ encl,
    uint16_t* __restrict__ w2h,  uint16_t* __restrict__ w2l,
    uint16_t* __restrict__ ch,   uint16_t* __restrict__ cl)
{
    const int stride = gridDim.x * blockDim.x;
    const int N1 = (T_DIM * B_DIM * H_DIM) >> 2;
    uint2 hi, lo;
    for (int i = blockIdx.x * blockDim.x + threadIdx.x; i < N1; i += stride) {
        float4 v = *(const float4*)&enc[(size_t)i * 4];
        cvt_split(v, hi, lo);
        *(uint2*)&ench[(size_t)i * 4] = hi;
        *(uint2*)&encl[(size_t)i * 4] = lo;
    }
    const int N2 = (H_DIM * H_DIM) >> 2;
    for (int i = blockIdx.x * blockDim.x + threadIdx.x; i < N2; i += stride) {
        int e = i * 4;
        int r = e >> 9, c = e & 511;
        float4 v = *(const float4*)&attn_W[(size_t)r * 2 * H_DIM + H_DIM + c];
        cvt_split(v, hi, lo);
        *(uint2*)&w2h[e] = hi;
        *(uint2*)&w2l[e] = lo;
        v = *(const float4*)&c1W[(size_t)r * H_DIM + c];
        cvt_split(v, hi, lo);
        *(uint2*)&ch[e] = hi;
        *(uint2*)&cl[e] = lo;
    }
}

// ================= enc GEMM: preconverted bf16x3, 128x128 tile ===========
// 3-stage cp.async pipeline, 64B swizzled rows, ONE sync per K-chunk, 2 CTA/SM.
static constexpr int TILE64   = 128 * 64;            // 8192 bytes per tile
static constexpr int TGP_STAGE = 4 * TILE64;         // 32768
static constexpr int TGP_SMEM  = 3 * TGP_STAGE;      // 98304

__global__ void __launch_bounds__(256, 2) tgemm_pre(
    const uint16_t* __restrict__ Ah, const uint16_t* __restrict__ Al,
    const uint16_t* __restrict__ Bh, const uint16_t* __restrict__ Bl,
    int K, int lda, int ldb,
    const float* __restrict__ add_bh, const float* __restrict__ bias_n,
    const float* __restrict__ wgt_n,
    float* __restrict__ red_out, float* __restrict__ Cts)
{
    extern __shared__ char smem[];
    const uint32_t sb = smem_u32(smem);
    const int tid = threadIdx.x, lane = tid & 31, warp = tid >> 5;
    const int wy = warp >> 2, wx = warp & 3;
    const int m0 = blockIdx.y * 128, n0 = blockIdx.x * 128;

    float acc[4][4][4];
#pragma unroll
    for (int i = 0; i < 4; i++)
#pragma unroll
        for (int j = 0; j < 4; j++)
#pragma unroll
            for (int q = 0; q < 4; q++) acc[i][j][q] = 0.0f;

    const int nchunk = K >> 5;

    auto load_stage = [&](int st, int c) {
        const int k0 = c << 5;
        const uint32_t base = sb + st * TGP_STAGE;
#pragma unroll
        for (int i = 0; i < 2; i++) {
            int id  = tid + (i << 8);
            int row = id >> 2;
            int ch  = id & 3;
            uint32_t off = row * 64 + ((ch ^ ((row >> 1) & 3)) << 4);
            size_t ao = (size_t)(m0 + row) * lda + k0 + ch * 8;
            size_t bo = (size_t)(n0 + row) * ldb + k0 + ch * 8;
            CP_ASYNC16(base + off,              (const void*)&Ah[ao]);
            CP_ASYNC16(base + TILE64 + off,     (const void*)&Al[ao]);
            CP_ASYNC16(base + 2 * TILE64 + off, (const void*)&Bh[bo]);
            CP_ASYNC16(base + 3 * TILE64 + off, (const void*)&Bl[bo]);
        }
    };
    auto compute = [&](int st) {
        const uint32_t s0 = sb + st * TGP_STAGE;
        const int q = lane >> 3, r = lane & 7;
#pragma unroll
        for (int ks = 0; ks < 32; ks += 16) {
            uint32_t a_hi[4][4], a_lo[4][4], b_hi[4][2], b_lo[4][2];
            {
                int arow = wy * 64 + ((q & 1) ? 8 : 0) + r;
                int acol = ks + ((q & 2) ? 8 : 0);
                uint32_t addr = s0 + arow * 64
                              + ((((acol >> 3) ^ ((arow >> 1) & 3))) << 4);
#pragma unroll
                for (int mt = 0; mt < 4; mt++) {
                    ldsm4(a_hi[mt], addr + mt * (16 * 64));
                    ldsm4(a_lo[mt], addr + TILE64 + mt * (16 * 64));
                }
            }
            {
                int brow = wx * 32 + ((q & 2) ? 8 : 0) + r;
                int bcol = ks + ((q & 1) ? 8 : 0);
                uint32_t addr = s0 + 2 * TILE64 + brow * 64
                              + ((((bcol >> 3) ^ ((brow >> 1) & 3))) << 4);
#pragma unroll
                for (int np = 0; np < 2; np++) {
                    ldsm4(&b_hi[np * 2][0], addr + np * (16 * 64));
                    ldsm4(&b_lo[np * 2][0], addr + TILE64 + np * (16 * 64));
                }
            }
#pragma unroll
            for (int mt = 0; mt < 4; mt++)
#pragma unroll
                for (int nt = 0; nt < 4; nt++)
                    mma_bf16(acc[mt][nt], a_hi[mt], b_hi[nt]);
#pragma unroll
            for (int mt = 0; mt < 4; mt++)
#pragma unroll
                for (int nt = 0; nt < 4; nt++)
                    mma_bf16(acc[mt][nt], a_hi[mt], b_lo[nt]);
#pragma unroll
            for (int mt = 0; mt < 4; mt++)
#pragma unroll
                for (int nt = 0; nt < 4; nt++)
                    mma_bf16(acc[mt][nt], a_lo[mt], b_hi[nt]);
        }
    };

    load_stage(0, 0); CP_COMMIT();
    if (nchunk > 1) { load_stage(1, 1); CP_COMMIT(); }
    for (int c = 0; c < nchunk; c++) {
        if (c + 1 < nchunk) { CP_WAIT(1); } else { CP_WAIT(0); }
        __syncthreads();
        compute(c % 3);
        if (c + 2 < nchunk) { load_stage((c + 2) % 3, c + 2); CP_COMMIT(); }
    }
    __syncthreads();

    const int g = lane >> 2, tig = lane & 3;

    if (red_out) {
        float* red = (float*)smem;
#pragma unroll
        for (int mt = 0; mt < 4; mt++) {
            int rl0 = wy * 64 + mt * 16 + g;
            int rl1 = rl0 + 8;
            int b0 = (m0 + rl0) & 63, b1 = (m0 + rl1) & 63;
            float p0 = 0.f, p1 = 0.f;
#pragma unroll
            for (int nt = 0; nt < 4; nt++) {
                int col = n0 + wx * 32 + nt * 8 + tig * 2;
#pragma unroll
                for (int cc = 0; cc < 2; cc++) {
                    int cg = col + cc;
                    float bias = bias_n[cg];
                    float a0 = add_bh[(size_t)b0 * H_DIM + cg];
                    float a1 = add_bh[(size_t)b1 * H_DIM + cg];
                    float w  = wgt_n[cg];
                    p0 += w * tanhf(acc[mt][nt][cc]     + a0 + bias);
                    p1 += w * tanhf(acc[mt][nt][2 + cc] + a1 + bias);
                }
            }
            p0 += __shfl_xor_sync(0xffffffffu, p0, 1);
            p0 += __shfl_xor_sync(0xffffffffu, p0, 2);
            p1 += __shfl_xor_sync(0xffffffffu, p1, 1);
            p1 += __shfl_xor_sync(0xffffffffu, p1, 2);
            if (tig == 0) { red[wx * 128 + rl0] = p0; red[wx * 128 + rl1] = p1; }
        }
        __syncthreads();
        if (tid < 128) {
            float s = red[tid] + red[128 + tid] + red[256 + tid] + red[384 + tid];
            int m = m0 + tid;
            red_out[(size_t)blockIdx.x * (B_DIM * T_DIM) + (m & 63) * T_DIM + (m >> 6)] = s;
        }
        return;
    }

#pragma unroll
    for (int mt = 0; mt < 4; mt++) {
        int row0 = m0 + wy * 64 + mt * 16 + g;
#pragma unroll
        for (int nt = 0; nt < 4; nt++) {
            int col = n0 + wx * 32 + nt * 8 + tig * 2;
            float bv0 = bias_n[col], bv1 = bias_n[col + 1];
            *(float2*)&Cts[(size_t)row0 * H_DIM + col] =
                make_float2(tanhf(acc[mt][nt][0] + bv0), tanhf(acc[mt][nt][1] + bv1));
            *(float2*)&Cts[(size_t)(row0 + 8) * H_DIM + col] =
                make_float2(tanhf(acc[mt][nt][2] + bv0), tanhf(acc[mt][nt][3] + bv1));
        }
    }
}

// ================= small GEMM: cvt-in-kernel bf16x3, 64x128 tile =========
static constexpr int ROWB = 80;
static constexpr int TILEA  = 64 * ROWB;
static constexpr int TILEB  = 128 * ROWB;
static constexpr int STAGEB = 2 * TILEA + 2 * TILEB;  // 30720
static constexpr int TGC_SMEM = 2 * STAGEB;           // 61440

__global__ void __launch_bounds__(256, 2) tgemm_cvt(
    const float* __restrict__ A, const float* __restrict__ B, float* __restrict__ C,
    int M_A, int K, int lda, int ldb, int ldc,
    const float* __restrict__ pb, float* __restrict__ pmax, float* __restrict__ psum)
{
    extern __shared__ char smem[];
    const uint32_t sb = smem_u32(smem);
    const int tid = threadIdx.x, lane = tid & 31, warp = tid >> 5;
    const int wy = warp >> 2, wx = warp & 3;
    const int m0 = blockIdx.y * 64, n0 = blockIdx.x * 128;

    float acc[2][4][4];
#pragma unroll
    for (int i = 0; i < 2; i++)
#pragma unroll
        for (int j = 0; j < 4; j++)
#pragma unroll
            for (int q = 0; q < 4; q++) acc[i][j][q] = 0.0f;

    const int nchunk = K >> 5;
    float4 ra[2], rb[4];

    auto load_regs = [&](int c) {
        const int k0 = c << 5;
#pragma unroll
        for (int i = 0; i < 2; i++) {
            int id = tid + (i << 8);
            int row = id >> 3, kq = id & 7;
            ra[i] = (m0 + row < M_A)
                  ? *(const float4*)&A[(size_t)(m0 + row) * lda + k0 + (kq << 2)]
                  : make_float4(0.f, 0.f, 0.f, 0.f);
        }
#pragma unroll
        for (int i = 0; i < 4; i++) {
            int id = tid + (i << 8);
            int row = id >> 3, kq = id & 7;
            rb[i] = *(const float4*)&B[(size_t)(n0 + row) * ldb + k0 + (kq << 2)];
        }
    };
    auto store_smem = [&](int st) {
        char* base = smem + st * STAGEB;
        uint2 hi, lo;
#pragma unroll
        for (int i = 0; i < 2; i++) {
            int id = tid + (i << 8);
            int row = id >> 3, kq = id & 7;
            int off = row * ROWB + (kq << 3);
            cvt_split(ra[i], hi, lo);
            *(uint2*)(base + off)         = hi;
            *(uint2*)(base + TILEA + off) = lo;
        }
#pragma unroll
        for (int i = 0; i < 4; i++) {
            int id = tid + (i << 8);
            int row = id >> 3, kq = id & 7;
            int off = row * ROWB + (kq << 3);
            cvt_split(rb[i], hi, lo);
            *(uint2*)(base + 2 * TILEA + off)         = hi;
            *(uint2*)(base + 2 * TILEA + TILEB + off) = lo;
        }
    };
    auto compute = [&](int st) {
        const uint32_t s0 = sb + st * STAGEB;
        const int q = lane >> 3, r = lane & 7;
#pragma unroll
        for (int ks = 0; ks < 32; ks += 16) {
            uint32_t a_hi[2][4], a_lo[2][4], b_hi[4][2], b_lo[4][2];
            {
                int arow = wy * 32 + ((q & 1) ? 8 : 0) + r;
                int acol = ks + ((q & 2) ? 8 : 0);
                uint32_t addr = s0 + arow * ROWB + acol * 2;
#pragma unroll
                for (int mt = 0; mt < 2; mt++) {
                    ldsm4(a_hi[mt], addr + mt * (16 * ROWB));
                    ldsm4(a_lo[mt], addr + TILEA + mt * (16 * ROWB));
                }
            }
            {
                int brow = wx * 32 + ((q & 2) ? 8 : 0) + r;
                int bcol = ks + ((q & 1) ? 8 : 0);
                uint32_t addr = s0 + 2 * TILEA + brow * ROWB + bcol * 2;
#pragma unroll
                for (int np = 0; np < 2; np++) {
                    ldsm4(&b_hi[np * 2][0], addr + np * (16 * ROWB));
                    ldsm4(&b_lo[np * 2][0], addr + TILEB + np * (16 * ROWB));
                }
            }
#pragma unroll
            for (int mt = 0; mt < 2; mt++)
#pragma unroll
                for (int nt = 0; nt < 4; nt++)
                    mma_bf16(acc[mt][nt], a_hi[mt], b_hi[nt]);
#pragma unroll
            for (int mt = 0; mt < 2; mt++)
#pragma unroll
                for (int nt = 0; nt < 4; nt++)
                    mma_bf16(acc[mt][nt], a_hi[mt], b_lo[nt]);
#pragma unroll
            for (int mt = 0; mt < 2; mt++)
#pragma unroll
                for (int nt = 0; nt < 4; nt++)
                    mma_bf16(acc[mt][nt], a_lo[mt], b_hi[nt]);
        }
    };

    load_regs(0);
    store_smem(0);
    if (nchunk > 1) load_regs(1);
    __syncthreads();
    for (int c = 0; c < nchunk; c++) {
        if (c + 1 < nchunk) store_smem((c + 1) & 1);
        if (c + 2 < nchunk) load_regs(c + 2);
        compute(c & 1);
        __syncthreads();
    }

    const int g = lane >> 2, tig = lane & 3;

    if (pmax) {
        float lm[4], ls[4];
#pragma unroll
        for (int sl = 0; sl < 4; sl++) { lm[sl] = -1e30f; ls[sl] = 0.0f; }
#pragma unroll
        for (int mt = 0; mt < 2; mt++) {
            int r0 = m0 + wy * 32 + mt * 16 + g;
            int r1 = r0 + 8;
#pragma unroll
            for (int nt = 0; nt < 4; nt++) {
                int col = n0 + wx * 32 + nt * 8 + tig * 2;
                float pb0 = pb[col], pb1 = pb[col + 1];
                float v00 = acc[mt][nt][0], v01 = acc[mt][nt][1];
                float v10 = acc[mt][nt][2], v11 = acc[mt][nt][3];
                *(float2*)&C[(size_t)r0 * ldc + col] = make_float2(v00, v01);
                *(float2*)&C[(size_t)r1 * ldc + col] = make_float2(v10, v11);
                softmerge(lm[mt * 2], ls[mt * 2], v00 + pb0, 1.0f);
                softmerge(lm[mt * 2], ls[mt * 2], v01 + pb1, 1.0f);
                softmerge(lm[mt * 2 + 1], ls[mt * 2 + 1], v10 + pb0, 1.0f);
                softmerge(lm[mt * 2 + 1], ls[mt * 2 + 1], v11 + pb1, 1.0f);
            }
        }
#pragma unroll
        for (int d = 1; d <= 2; d <<= 1)
#pragma unroll
            for (int sl = 0; sl < 4; sl++) {
                float om = __shfl_xor_sync(0xffffffffu, lm[sl], d);
                float os = __shfl_xor_sync(0xffffffffu, ls[sl], d);
                softmerge(lm[sl], ls[sl], om, os);
            }
        float* pm = (float*)smem;
        float* ps = pm + 256;
        if (tig == 0) {
#pragma unroll
            for (int sl = 0; sl < 4; sl++) {
                int row = wy * 32 + sl * 8 + g;
                pm[wx * 64 + row] = lm[sl];
                ps[wx * 64 + row] = ls[sl];
            }
        }
        __syncthreads();
        if (tid < 64) {
            float m = pm[tid], s = ps[tid];
            softmerge(m, s, pm[64 + tid],  ps[64 + tid]);
            softmerge(m, s, pm[128 + tid], ps[128 + tid]);
            softmerge(m, s, pm[192 + tid], ps[192 + tid]);
            pmax[(size_t)blockIdx.x * B_DIM + tid] = m;
            psum[(size_t)blockIdx.x * B_DIM + tid] = s;
        }
        return;
    }

#pragma unroll
    for (int mt = 0; mt < 2; mt++) {
        int row0 = m0 + wy * 32 + mt * 16 + g;
#pragma unroll
        for (int nt = 0; nt < 4; nt++) {
            int col = n0 + wx * 32 + nt * 8 + tig * 2;
            if (row0 < M_A) {
                *(float2*)&C[(size_t)row0 * ldc + col] = make_float2(acc[mt][nt][0], acc[mt][nt][1]);
                *(float2*)&C[(size_t)(row0 + 8) * ldc + col] = make_float2(acc[mt][nt][2], acc[mt][nt][3]);
            }
        }
    }
}

// ================= elementwise / reduction kernels =================

__global__ void __launch_bounds__(128) k_attn(
    const float* __restrict__ part, const int* __restrict__ z,
    const float* __restrict__ emb,  const float* __restrict__ enc,
    float* __restrict__ ctx, float* __restrict__ x)
{
    int b = blockIdx.x, q = blockIdx.y, tid = threadIdx.x;
    __shared__ float al[T_DIM];
    __shared__ float sm[T_DIM];
    {
        int idx = b * T_DIM + tid;
        float v = part[idx] + part[B_DIM * T_DIM + idx]
                + part[2 * B_DIM * T_DIM + idx] + part[3 * B_DIM * T_DIM + idx];
        al[tid] = v; sm[tid] = v;
    }
    __syncthreads();
    for (int o = 64; o > 0; o >>= 1) { if (tid < o) sm[tid] = fmaxf(sm[tid], sm[tid + o]); __syncthreads(); }
    float mx = sm[0]; __syncthreads();
    { float e = expf(al[tid] - mx); al[tid] = e; sm[tid] = e; }
    __syncthreads();
    for (int o = 64; o > 0; o >>= 1) { if (tid < o) sm[tid] += sm[tid + o]; __syncthreads(); }
    float inv = 1.0f / sm[0];

    int h = q * 128 + tid;
    const float* eb = enc + (size_t)b * H_DIM + h;
    float acc = 0.0f;
#pragma unroll 8
    for (int t = 0; t < T_DIM; t++)
        acc += al[t] * eb[(size_t)t * B_DIM * H_DIM];
    acc *= inv;
    ctx[b * H_DIM + h] = acc;
    x[(size_t)b * (E_DIM + H_DIM) + E_DIM + h] = acc;
    if (q == 0) {
        x[(size_t)b * (E_DIM + H_DIM) + tid]       = emb[(size_t)z[b] * E_DIM + tid];
        x[(size_t)b * (E_DIM + H_DIM) + 128 + tid] = emb[(size_t)z[b] * E_DIM + 128 + tid];
    }
}

__global__ void k_gru(const float* __restrict__ gi, const float* __restrict__ gh,
                      const float* __restrict__ bih, const float* __restrict__ bhh,
                      const float* __restrict__ h_prev, const float* __restrict__ ctx,
                      float* __restrict__ hnew, float* __restrict__ xp,
                      float* __restrict__ out)
{
    int b = blockIdx.x, h = threadIdx.x;
    const float* gib = gi + (size_t)b * 3 * H_DIM;
    const float* ghb = gh + (size_t)b * 3 * H_DIM;
    float ir  = gib[h]              + bih[h];
    float iz  = gib[H_DIM + h]      + bih[H_DIM + h];
    float in_ = gib[2 * H_DIM + h]  + bih[2 * H_DIM + h];
    float hr  = ghb[h]              + bhh[h];
    float hz  = ghb[H_DIM + h]      + bhh[H_DIM + h];
    float hn  = ghb[2 * H_DIM + h]  + bhh[2 * H_DIM + h];
    float r  = 1.0f / (1.0f + expf(-(ir + hr)));
    float zz = 1.0f / (1.0f + expf(-(iz + hz)));
    float n  = tanhf(in_ + r * hn);
    float hp = h_prev[b * H_DIM + h];
    float v  = (1.0f - zz) * n + zz * hp;
    hnew[b * H_DIM + h] = v;
    out[b * H_DIM + h] = v;
    out[B_DIM * H_DIM + b * H_DIM + h] = v;
    xp[b * 2 * H_DIM + h] = v;
    xp[b * 2 * H_DIM + H_DIM + h] = ctx[b * H_DIM + h];
}

__global__ void k_raw(const float* __restrict__ cs, const float* __restrict__ hnew,
                      float* __restrict__ raw)
{
    int warp = (blockIdx.x * blockDim.x + threadIdx.x) >> 5;
    int lane = threadIdx.x & 31;
    if (warp >= T_DIM * B_DIM) return;
    int b = warp % B_DIM;
    const float4* e4 = (const float4*)(cs + (size_t)warp * H_DIM);
    const float4* h4 = (const float4*)(hnew + (size_t)b * H_DIM);
    float s = 0.0f;
#pragma unroll
    for (int i = lane; i < H_DIM / 4; i += 32) {
        float4 e = e4[i], h = h4[i];
        s += e.x * h.x + e.y * h.y + e.z * h.z + e.w * h.w;
    }
#pragma unroll
    for (int o = 16; o > 0; o >>= 1) s += __shfl_down_sync(0xffffffffu, s, o);
    if (lane == 0) raw[b * T_DIM + (warp / B_DIM)] = s;
}

__global__ void k_copystats(const float* __restrict__ raw, const int* __restrict__ u_input,
                            int* __restrict__ cidx, float* __restrict__ cval,
                            float* __restrict__ stats)
{
    int b = blockIdx.x, t = threadIdx.x;
    __shared__ float sm[T_DIM];
    __shared__ float exm[T_DIM];
    __shared__ int   sidx[T_DIM];
    float v = raw[b * T_DIM + t];
    sm[t] = v; __syncthreads();
    for (int o = 64; o > 0; o >>= 1) { if (t < o) sm[t] = fmaxf(sm[t], sm[t + o]); __syncthreads(); }
    float cmax = sm[0]; __syncthreads();

    float e = expf(v - cmax);
    int tok = u_input[t * B_DIM + b];
    sidx[t] = (tok == 2) ? (V_DIM + t) : tok;
    float em = (tok != 0) ? e : 0.0f;
    exm[t] = em;

    sm[t] = e; __syncthreads();
    for (int o = 64; o > 0; o >>= 1) { if (t < o) sm[t] += sm[t + o]; __syncthreads(); }
    float total = sm[0]; __syncthreads();

    sm[t] = em; __syncthreads();
    for (int o = 64; o > 0; o >>= 1) { if (t < o) sm[t] += sm[t + o]; __syncthreads(); }
    float sum_exm = sm[0]; __syncthreads();

    int idx = sidx[t];
    bool first = true;
    for (int i = 0; i < t; i++) if (sidx[i] == idx) { first = false; break; }
    float a = 0.0f;
    if (first) {
        for (int i = t; i < T_DIM; i++) if (sidx[i] == idx) a += exm[i];
        cidx[b * T_DIM + t] = idx;
    } else {
        cidx[b * T_DIM + t] = -1;
    }
    cval[b * T_DIM + t] = a;

    sm[t] = a; __syncthreads();
    for (int o = 64; o > 0; o >>= 1) { if (t < o) sm[t] = fmaxf(sm[t], sm[t + o]); __syncthreads(); }
    if (t == 0) {
        stats[b * 8 + 0] = cmax;
        stats[b * 8 + 1] = total;
        stats[b * 8 + 2] = sum_exm;
        stats[b * 8 + 3] = sm[0];
    }
}

__global__ void __launch_bounds__(256) k_reduce(
    const float* __restrict__ pmax, const float* __restrict__ psum,
    float* __restrict__ stats)
{
    int b = blockIdx.x, tid = threadIdx.x;
    float m = -1e30f, s = 0.0f;
    for (int i = tid; i < NCTA_V; i += 256)
        softmerge(m, s, pmax[(size_t)i * B_DIM + b], psum[(size_t)i * B_DIM + b]);
    __shared__ float ms[256], ss[256];
    ms[tid] = m; ss[tid] = s; __syncthreads();
    for (int o = 128; o > 0; o >>= 1) {
        if (tid < o) {
            float mm = ms[tid], sv = ss[tid];
            softmerge(mm, sv, ms[tid + o], ss[tid + o]);
            ms[tid] = mm; ss[tid] = sv;
        }
        __syncthreads();
    }
    if (tid == 0) {
        float cmax = stats[b * 8 + 0];
        float total = stats[b * 8 + 1];
        float sum_exm = stats[b * 8 + 2];
        float smax = stats[b * 8 + 3];
        float mg = ms[0], sg = ss[0];
        float mc = logf(EPSC * total + (1.0f - EPSC) * smax) + cmax;
        float M = fmaxf(mg, mc);
        float A = expf(cmax - M);
        float S = sg * expf(mg - M)
                + A * (EPSC * total * (float)VT_DIM + (1.0f - EPSC) * sum_exm);
        stats[b * 8 + 4] = M;
        stats[b * 8 + 5] = S;
        stats[b * 8 + 6] = A;
    }
}

// vectorized final: 4 elements per thread
__global__ void __launch_bounds__(256) k_final(
    const float* __restrict__ gen, const float* __restrict__ projb,
    const float* __restrict__ stats, float* __restrict__ out)
{
    int i4 = blockIdx.x * blockDim.x + threadIdx.x;
    if (i4 >= (B_DIM * VT_DIM) / 4) return;
    int b = i4 / (VT_DIM / 4);
    int j = (i4 % (VT_DIM / 4)) * 4;
    float M = stats[b * 8 + 4];
    float S = stats[b * 8 + 5];
    float A = stats[b * 8 + 6];
    float total = stats[b * 8 + 1];
    float invS = 1.0f / S;
    float base = A * EPSC * total * invS;
    float4 r = make_float4(base, base, base, base);
    if (j < V_DIM) {
        float4 g = *(const float4*)&gen[(size_t)b * V_DIM + j];
        float4 p = *(const float4*)&projb[j];
        r.x += __expf(g.x + p.x - M) * invS;
        r.y += __expf(g.y + p.y - M) * invS;
        r.z += __expf(g.z + p.z - M) * invS;
        r.w += __expf(g.w + p.w - M) * invS;
    }
    *(float4*)&out[2 * B_DIM * H_DIM + (size_t)b * VT_DIM + j] = r;
}

__global__ void k_scatter(const int* __restrict__ cidx, const float* __restrict__ cval,
                          const float* __restrict__ stats, float* __restrict__ out)
{
    int b = blockIdx.x, t = threadIdx.x;
    int id = cidx[b * T_DIM + t];
    if (id >= 0) {
        float S = stats[b * 8 + 5];
        float A = stats[b * 8 + 6];
        out[2 * B_DIM * H_DIM + (size_t)b * VT_DIM + id] +=
            A * (1.0f - EPSC) * cval[b * T_DIM + t] / S;
    }
}

// ================= host launcher (R11 schedule) =================
extern "C" void kernel_launch(void* const* d_in, const int* in_sizes, int n_in,
                              void* d_out, int out_size)
{
    const float* u_enc  = (const float*)d_in[0];
    const int*   z_tm1  = (const int*)  d_in[1];
    const float* h0     = (const float*)d_in[2];
    const int*   u_inp  = (const int*)  d_in[3];
    const float* emb    = (const float*)d_in[4];
    const float* attn_W = (const float*)d_in[5];
    const float* attn_b = (const float*)d_in[6];
    const float* attn_v = (const float*)d_in[7];
    const float* gWih   = (const float*)d_in[8];
    const float* gWhh   = (const float*)d_in[9];
    const float* gbih   = (const float*)d_in[10];
    const float* gbhh   = (const float*)d_in[11];
    const float* projW  = (const float*)d_in[12];
    const float* projb  = (const float*)d_in[13];
    const float* c1W    = (const float*)d_in[14];
    const float* c1b    = (const float*)d_in[15];
    float* out = (float*)d_out;

    float* base = nullptr;
    cudaGetSymbolAddress((void**)&base, g_scratch);
    float* spart = base + OFF_SPART;
    float* raw   = base + OFF_RAW;
    float* hW1   = base + OFF_HW1;
    float* ctx   = base + OFF_CTX;
    float* x     = base + OFF_X;
    float* gi    = base + OFF_GI;
    float* gh    = base + OFF_GH;
    float* hnew  = base + OFF_HNEW;
    float* xp    = base + OFF_XP;
    float* pmax  = base + OFF_PMAX;
    float* psum  = base + OFF_PSUM;
    float* gen   = base + OFF_GEN;
    int*   cidx  = (int*)(base + OFF_CIDX);
    float* cval  = base + OFF_CVAL;
    float* stats = base + OFF_STATS;
    float* cs    = base + OFF_CS;
    uint16_t* ench = (uint16_t*)(base + OFF_ENCH);
    uint16_t* encl = (uint16_t*)(base + OFF_ENCL);
    uint16_t* w2h  = (uint16_t*)(base + OFF_W2H);
    uint16_t* w2l  = (uint16_t*)(base + OFF_W2L);
    uint16_t* c1h  = (uint16_t*)(base + OFF_C1H);
    uint16_t* c1l  = (uint16_t*)(base + OFF_C1L);

    static cudaStream_t s1 = nullptr;
    static cudaEvent_t evFork, evPre, evHW1, evGh, evGru, evCst;
    if (!s1) {
        cudaStreamCreateWithFlags(&s1, cudaStreamNonBlocking);
        cudaEventCreateWithFlags(&evFork, cudaEventDisableTiming);
        cudaEventCreateWithFlags(&evPre,  cudaEventDisableTiming);
        cudaEventCreateWithFlags(&evHW1,  cudaEventDisableTiming);
        cudaEventCreateWithFlags(&evGh,   cudaEventDisableTiming);
        cudaEventCreateWithFlags(&evGru,  cudaEventDisableTiming);
        cudaEventCreateWithFlags(&evCst,  cudaEventDisableTiming);
        cudaFuncSetAttribute(tgemm_pre, cudaFuncAttributeMaxDynamicSharedMemorySize, TGP_SMEM);
        cudaFuncSetAttribute(tgemm_cvt, cudaFuncAttributeMaxDynamicSharedMemorySize, TGC_SMEM);
    }

    const int MROWS = T_DIM * B_DIM;  // 8192

    cudaEventRecord(evFork, 0);
    cudaStreamWaitEvent(s1, evFork, 0);

    // s1: hW1 ; gh (depend only on h0)
    tgemm_cvt<<<dim3(H_DIM / 128, 1), 256, TGC_SMEM, s1>>>(
        h0, attn_W, hW1, B_DIM, H_DIM, H_DIM, 2 * H_DIM, H_DIM, nullptr, nullptr, nullptr);
    cudaEventRecord(evHW1, s1);
    tgemm_cvt<<<dim3(3 * H_DIM / 128, 1), 256, TGC_SMEM, s1>>>(
        h0, gWhh, gh, B_DIM, H_DIM, H_DIM, H_DIM, 3 * H_DIM, nullptr, nullptr, nullptr);
    cudaEventRecord(evGh, s1);

    // s0: preconvert (vectorized)
    k_preconv<<<1024, 256>>>(u_enc, attn_W, c1W, ench, encl, w2h, w2l, c1h, c1l);
    cudaEventRecord(evPre, 0);

    // s1: copy GEMM -> cs (concurrent with energy GEMM, R11 schedule)
    cudaStreamWaitEvent(s1, evPre, 0);
    tgemm_pre<<<dim3(H_DIM / 128, MROWS / 128), 256, TGP_SMEM, s1>>>(
        ench, encl, c1h, c1l, H_DIM, H_DIM, H_DIM,
        nullptr, c1b, nullptr, nullptr, cs);

    // s0: energy GEMM + attn
    cudaStreamWaitEvent(0, evHW1, 0);
    tgemm_pre<<<dim3(H_DIM / 128, MROWS / 128), 256, TGP_SMEM>>>(
        ench, encl, w2h, w2l, H_DIM, H_DIM, H_DIM,
        hW1, attn_b, attn_v, spart, nullptr);
    k_attn<<<dim3(B_DIM, 4), 128>>>(spart, z_tm1, emb, u_enc, ctx, x);

    // s0: gi GEMM ; gru
    tgemm_cvt<<<dim3(3 * H_DIM / 128, 1), 256, TGC_SMEM>>>(
        x, gWih, gi, B_DIM, E_DIM + H_DIM, E_DIM + H_DIM, E_DIM + H_DIM, 3 * H_DIM,
        nullptr, nullptr, nullptr);
    cudaStreamWaitEvent(0, evGh, 0);
    k_gru<<<B_DIM, H_DIM>>>(gi, gh, gbih, gbhh, h0, ctx, hnew, xp, out);
    cudaEventRecord(evGru, 0);

    // s1: raw + copystats (hidden under proj GEMM)
    cudaStreamWaitEvent(s1, evGru, 0);
    k_raw<<<MROWS / 8, 256, 0, s1>>>(cs, hnew, raw);
    k_copystats<<<B_DIM, T_DIM, 0, s1>>>(raw, u_inp, cidx, cval, stats);
    cudaEventRecord(evCst, s1);

    // s0: proj GEMM with fused store + softmax partials
    tgemm_cvt<<<dim3(NCTA_V, 1), 256, TGC_SMEM>>>(
        xp, projW, gen, B_DIM, 2 * H_DIM, 2 * H_DIM, 2 * H_DIM, V_DIM,
        projb, pmax, psum);

    // join + tail
    cudaStreamWaitEvent(0, evCst, 0);
    k_reduce<<<B_DIM, 256>>>(pmax, psum, stats);
    k_final<<<(B_DIM * VT_DIM / 4 + 255) / 256, 256>>>(gen, projb, stats, out);
    k_scatter<<<B_DIM, T_DIM>>>(cidx, cval, stats, out);
}